// round 15
// baseline (speedup 1.0000x reference)
#include <cuda_runtime.h>

#define TT 1024
#define OO 512
#define DD 256
#define HH 512

__device__ float g_ht[TT * HH];   // z_t @ W1[:D]            [1024,512]
__device__ float g_ho[OO * HH];   // z_o @ W1[D:] + b1       [512,512]
__device__ float g_ct[TT];        // 0.505 * <ht[t], W2>
__device__ float g_co[OO];        // 0.505 * <ho[o], W2> + b2
__device__ float g_p1[TT * OO];   // pair partial for h-half 1

typedef unsigned long long u64;

__device__ __forceinline__ u64 add2(u64 a, u64 b) {
    u64 d; asm("add.rn.f32x2 %0,%1,%2;" : "=l"(d) : "l"(a), "l"(b)); return d;
}
__device__ __forceinline__ u64 fma2(u64 a, u64 b, u64 c) {
    u64 d; asm("fma.rn.f32x2 %0,%1,%2,%3;" : "=l"(d) : "l"(a), "l"(b), "l"(c)); return d;
}

// ---------------------------------------------------------------------------
// Fused GEMM over combined M=1536: rows [0,1024)=z_t@W1[:D],
// [1024,1536)=z_o@W1[D:]+b1.
// Classic scalar-FFMA tiling: BM=64, BN=64, BK=16, 256 threads, micro 4m x 4n.
// Per warp-k: 2 LDS.128 + 16 FFMA (floors: fma 11.8us == crossbar 11.8us).
// Grid (8 n-tiles, 24 m-tiles) = 192 CTAs -> 10.4 warps/SM.
// Double-buffered smem, 1 sync per 16-k block.
// ---------------------------------------------------------------------------
__global__ __launch_bounds__(256) void gemm_kernel(
    const float* __restrict__ z_t, const float* __restrict__ z_o,
    const float* __restrict__ W1,  const float* __restrict__ b1)
{
    __shared__ float As[2][16][68];   // [buf][k][m]; 272B row (16B mult)
    __shared__ float Bs[2][16][68];   // [buf][k][n]

    const int tid = threadIdx.x;
    const int mt  = blockIdx.y;             // 0..23
    const int n0  = blockIdx.x << 6;        // 0..448
    const bool isHo = (mt >= 16);
    const int m0 = (isHo ? (mt - 16) : mt) << 6;
    const float* A = isHo ? z_o : z_t;
    const float* B = isHo ? (W1 + (u64)DD * HH) : W1;
    float* C = isHo ? g_ho : g_ht;

    // A staging: m row = tid&63, k offset = (tid>>6)*4, one float4 along k
    const int am  = tid & 63;
    const int ak4 = (tid >> 6) << 2;        // 0,4,8,12
    // B staging: k row = tid>>4 (0..15), n = (tid&15)*4, one float4
    const int bk  = tid >> 4;
    const int bn4 = (tid & 15) << 2;

    // compute: m quad at ty*4, n quad at tx*4
    const int tx = tid & 15;
    const int ty = tid >> 4;                // 0..15

    float acc[4][4];
    #pragma unroll
    for (int i = 0; i < 4; i++)
        #pragma unroll
        for (int j = 0; j < 4; j++) acc[i][j] = 0.f;

    const float* aptr = &A[(u64)(m0 + am) * DD + ak4];
    const float* bptr = &B[(u64)bk * HH + n0 + bn4];

    float4 va, vb;

    // ---- prologue: stage 0 ----
    va = *reinterpret_cast<const float4*>(aptr);
    vb = *reinterpret_cast<const float4*>(bptr);
    As[0][ak4 + 0][am] = va.x; As[0][ak4 + 1][am] = va.y;
    As[0][ak4 + 2][am] = va.z; As[0][ak4 + 3][am] = va.w;
    *reinterpret_cast<float4*>(&Bs[0][bk][bn4]) = vb;
    __syncthreads();

    #pragma unroll 1
    for (int kb = 0; kb < 16; kb++) {
        const int cur = kb & 1, nxt = cur ^ 1;

        if (kb < 15) {   // next stage's global loads, hidden under compute
            va = *reinterpret_cast<const float4*>(aptr + ((kb + 1) << 4));
            vb = *reinterpret_cast<const float4*>(bptr + (u64)((kb + 1) << 4) * HH);
        }

        #pragma unroll
        for (int k = 0; k < 16; k++) {
            float4 af = *reinterpret_cast<const float4*>(&As[cur][k][ty << 2]);
            float4 bf = *reinterpret_cast<const float4*>(&Bs[cur][k][tx << 2]);
            acc[0][0] += af.x * bf.x; acc[0][1] += af.x * bf.y;
            acc[0][2] += af.x * bf.z; acc[0][3] += af.x * bf.w;
            acc[1][0] += af.y * bf.x; acc[1][1] += af.y * bf.y;
            acc[1][2] += af.y * bf.z; acc[1][3] += af.y * bf.w;
            acc[2][0] += af.z * bf.x; acc[2][1] += af.z * bf.y;
            acc[2][2] += af.z * bf.z; acc[2][3] += af.z * bf.w;
            acc[3][0] += af.w * bf.x; acc[3][1] += af.w * bf.y;
            acc[3][2] += af.w * bf.z; acc[3][3] += af.w * bf.w;
        }

        if (kb < 15) {   // store into the other buffer, then sync
            As[nxt][ak4 + 0][am] = va.x; As[nxt][ak4 + 1][am] = va.y;
            As[nxt][ak4 + 2][am] = va.z; As[nxt][ak4 + 3][am] = va.w;
            *reinterpret_cast<float4*>(&Bs[nxt][bk][bn4]) = vb;
            __syncthreads();
        }
    }

    float4 bv = make_float4(0.f, 0.f, 0.f, 0.f);
    if (isHo) bv = *reinterpret_cast<const float4*>(&b1[n0 + (tx << 2)]);

    #pragma unroll
    for (int i = 0; i < 4; i++) {
        float4 r = make_float4(acc[i][0] + bv.x, acc[i][1] + bv.y,
                               acc[i][2] + bv.z, acc[i][3] + bv.w);
        int row = m0 + (ty << 2) + i;
        *reinterpret_cast<float4*>(&C[(u64)row * HH + n0 + (tx << 2)]) = r;
    }
}

// ---------------------------------------------------------------------------
// Per-row linear terms: ct[t] = 0.505*<ht[t],W2>, co[o] = 0.505*<ho[o],W2>+b2
// ---------------------------------------------------------------------------
__global__ __launch_bounds__(256) void reduce_kernel(
    const float* __restrict__ W2, const float* __restrict__ b2)
{
    int warp = (blockIdx.x * blockDim.x + threadIdx.x) >> 5;
    int lane = threadIdx.x & 31;
    const float* row;
    float* dst;
    float extra = 0.f;
    if (warp < TT) { row = g_ht + (u64)warp * HH; dst = g_ct + warp; }
    else { row = g_ho + (u64)(warp - TT) * HH; dst = g_co + (warp - TT); extra = b2[0]; }
    float s = 0.f;
    #pragma unroll
    for (int i = 0; i < 4; i++) {
        float4 v = *reinterpret_cast<const float4*>(&row[(lane + 32 * i) << 2]);
        float4 w = *reinterpret_cast<const float4*>(&W2[(lane + 32 * i) << 2]);
        s += v.x * w.x + v.y * w.y + v.z * w.z + v.w * w.w;
    }
    #pragma unroll
    for (int off = 16; off; off >>= 1) s += __shfl_xor_sync(0xffffffffu, s, off);
    if (lane == 0) *dst = 0.505f * s + extra;
}

// ---------------------------------------------------------------------------
// Pairwise kernel, SPLIT over H: grid.z=2, each half covers 4 chunks (256 h).
// z=0 writes out including ct+co; z=1 writes partials to g_p1; combine adds.
// 64x64 tile, 256 threads, micro 4t x 4o, 256 CTAs -> ~14 warps/SM.
// Depth-2 register pipeline over hq. Packed f32x2 inner (2 fma + 2 alu / pair).
// ---------------------------------------------------------------------------
__global__ __launch_bounds__(256) void pair_kernel(
    const float* __restrict__ W2, float* __restrict__ out)
{
    __shared__ float4 sA[16][65];      // [hq][t], float4 = 4 h
    __shared__ float4 sB[16][65];      // [hq][o]
    __shared__ float4 sW[HH / 4];      // 0.495*W2 quads (full, loaded once)

    const int tid = threadIdx.x;
    const int tx = tid & 15;           // o lane (o = tx + 16j)
    const int ty = tid >> 4;           // t lane (t = ty + 16i)
    const int t0 = blockIdx.y << 6;
    const int o0 = blockIdx.x << 6;
    const int z  = blockIdx.z;         // h-half
    const int cz = z << 2;             // first chunk of this half

    if (tid < HH / 4) {
        float4 w = *reinterpret_cast<const float4*>(&W2[tid << 2]);
        w.x *= 0.495f; w.y *= 0.495f; w.z *= 0.495f; w.w *= 0.495f;
        sW[tid] = w;
    }

    u64 acc[4][4];
    #pragma unroll
    for (int i = 0; i < 4; i++)
        #pragma unroll
        for (int j = 0; j < 4; j++) acc[i][j] = 0ull;

    const int hs = tid & 15;           // hq for staging
    const int ts = tid >> 4;           // 0..15
    const u64 SMASK = 0x7fffffff7fffffffULL;

    const float* pa[4];
    const float* pb[4];
    #pragma unroll
    for (int r = 0; r < 4; r++) {
        pa[r] = &g_ht[(u64)(t0 + ts + (r << 4)) * HH + (cz << 6) + (hs << 2)];
        pb[r] = &g_ho[(u64)(o0 + ts + (r << 4)) * HH + (cz << 6) + (hs << 2)];
    }

    float4 va[4], vb[4];
    #pragma unroll
    for (int r = 0; r < 4; r++) {
        va[r] = *reinterpret_cast<const float4*>(pa[r]);
        vb[r] = *reinterpret_cast<const float4*>(pb[r]);
    }

    #pragma unroll 1
    for (int cc = 0; cc < 4; cc++) {   // 4 chunks of 64 h
        const int c = cz + cc;
        __syncthreads();
        #pragma unroll
        for (int r = 0; r < 4; r++) {
            sA[hs][ts + (r << 4)] = va[r];
            sB[hs][ts + (r << 4)] = vb[r];
        }
        __syncthreads();

        if (cc < 3) {                  // prefetch next chunk under compute
            int off = (cc + 1) << 6;
            #pragma unroll
            for (int r = 0; r < 4; r++) {
                va[r] = *reinterpret_cast<const float4*>(pa[r] + off);
                vb[r] = *reinterpret_cast<const float4*>(pb[r] + off);
            }
        }

        // ---- depth-2 pipelined hq loop ----
        ulonglong2 w = *reinterpret_cast<const ulonglong2*>(&sW[c << 4]);
        ulonglong2 a[4], b[4];
        #pragma unroll
        for (int i = 0; i < 4; i++)
            a[i] = *reinterpret_cast<const ulonglong2*>(&sA[0][ty + (i << 4)]);
        #pragma unroll
        for (int j = 0; j < 4; j++)
            b[j] = *reinterpret_cast<const ulonglong2*>(&sB[0][tx + (j << 4)]);

        #pragma unroll
        for (int hq = 0; hq < 16; hq++) {
            ulonglong2 wn, an[4], bn[4];
            if (hq < 15) {
                wn = *reinterpret_cast<const ulonglong2*>(&sW[(c << 4) + hq + 1]);
                #pragma unroll
                for (int i = 0; i < 4; i++)
                    an[i] = *reinterpret_cast<const ulonglong2*>(&sA[hq + 1][ty + (i << 4)]);
                #pragma unroll
                for (int j = 0; j < 4; j++)
                    bn[j] = *reinterpret_cast<const ulonglong2*>(&sB[hq + 1][tx + (j << 4)]);
            }

            #pragma unroll
            for (int i = 0; i < 4; i++)
                #pragma unroll
                for (int j = 0; j < 4; j++) {
                    u64 x = add2(a[i].x, b[j].x) & SMASK;
                    acc[i][j] = fma2(x, w.x, acc[i][j]);
                    u64 y = add2(a[i].y, b[j].y) & SMASK;
                    acc[i][j] = fma2(y, w.y, acc[i][j]);
                }

            if (hq < 15) {
                w = wn;
                #pragma unroll
                for (int i = 0; i < 4; i++) a[i] = an[i];
                #pragma unroll
                for (int j = 0; j < 4; j++) b[j] = bn[j];
            }
        }
    }

    float* dst = z ? g_p1 : out;
    float ctv[4], cov[4];
    if (z == 0) {
        #pragma unroll
        for (int i = 0; i < 4; i++) ctv[i] = g_ct[t0 + ty + (i << 4)];
        #pragma unroll
        for (int j = 0; j < 4; j++) cov[j] = g_co[o0 + tx + (j << 4)];
    } else {
        #pragma unroll
        for (int i = 0; i < 4; i++) ctv[i] = 0.f;
        #pragma unroll
        for (int j = 0; j < 4; j++) cov[j] = 0.f;
    }
    #pragma unroll
    for (int i = 0; i < 4; i++)
        #pragma unroll
        for (int j = 0; j < 4; j++) {
            float2 p = *reinterpret_cast<float2*>(&acc[i][j]);
            dst[(u64)(t0 + ty + (i << 4)) * OO + o0 + tx + (j << 4)]
                = ctv[i] + cov[j] + p.x + p.y;
        }
}

// ---------------------------------------------------------------------------
// Combine: out += g_p1 (both halves of the H split).
// ---------------------------------------------------------------------------
__global__ __launch_bounds__(256) void combine_kernel(float* __restrict__ out)
{
    int i = blockIdx.x * 256 + threadIdx.x;     // float4 index
    float4* o4 = reinterpret_cast<float4*>(out);
    const float4* p4 = reinterpret_cast<const float4*>(g_p1);
    float4 a = o4[i], b = p4[i];
    a.x += b.x; a.y += b.y; a.z += b.z; a.w += b.w;
    o4[i] = a;
}

extern "C" void kernel_launch(void* const* d_in, const int* in_sizes, int n_in,
                              void* d_out, int out_size)
{
    const float* z_t = (const float*)d_in[0];   // [1024,256]
    const float* z_o = (const float*)d_in[1];   // [512,256]
    const float* W1  = (const float*)d_in[2];   // [512,512]
    const float* b1  = (const float*)d_in[3];   // [512]
    const float* W2  = (const float*)d_in[4];   // [512,1]
    const float* b2  = (const float*)d_in[5];   // [1]
    float* out = (float*)d_out;                 // [1024,512]

    gemm_kernel<<<dim3(8, 24), 256>>>(z_t, z_o, W1, b1);
    reduce_kernel<<<192, 256>>>(W2, b2);
    pair_kernel<<<dim3(OO / 64, TT / 64, 2), 256>>>(W2, out);
    combine_kernel<<<TT * OO / 1024, 256>>>(out);
}

// round 16
// speedup vs baseline: 1.1085x; 1.1085x over previous
#include <cuda_runtime.h>

#define TT 1024
#define OO 512
#define DD 256
#define HH 512

// k-split GEMM planes (summed on the fly by consumers; no atomics needed)
__device__ float g_ht0[TT * HH];
__device__ float g_ht1[TT * HH];
__device__ float g_ho0[OO * HH];
__device__ float g_ho1[OO * HH];
__device__ float g_ct[TT];        // 0.505 * <ht[t], W2>
__device__ float g_co[OO];        // 0.505 * <ho[o], W2> + b2

typedef unsigned long long u64;

__device__ __forceinline__ u64 add2(u64 a, u64 b) {
    u64 d; asm("add.rn.f32x2 %0,%1,%2;" : "=l"(d) : "l"(a), "l"(b)); return d;
}
__device__ __forceinline__ u64 fma2(u64 a, u64 b, u64 c) {
    u64 d; asm("fma.rn.f32x2 %0,%1,%2,%3;" : "=l"(d) : "l"(a), "l"(b), "l"(c)); return d;
}
__device__ __forceinline__ float4 f4add(float4 a, float4 b) {
    return make_float4(a.x + b.x, a.y + b.y, a.z + b.z, a.w + b.w);
}

// ---------------------------------------------------------------------------
// Zero the output (pair planes accumulate into it atomically).
// ---------------------------------------------------------------------------
__global__ __launch_bounds__(256) void zero_kernel(float4* __restrict__ out4)
{
    out4[blockIdx.x * 256 + threadIdx.x] = make_float4(0.f, 0.f, 0.f, 0.f);
}

// ---------------------------------------------------------------------------
// Fused GEMM, K-SPLIT by 2 (grid.z): plane z covers k in [z*128,(z+1)*128).
// rows [0,1024)=z_t@W1[:D] -> g_ht{z}, [1024,1536)=z_o@W1[D:](+b1 on z=0)
// -> g_ho{z}. BM=64, BN=32, BK=32, 128 threads, micro 4m x 4n, depth-2
// software-pipelined inner (R11 body). Grid (16,24,2)=768 CTAs, 20.7 w/SM.
// ---------------------------------------------------------------------------
__global__ __launch_bounds__(128) void gemm_kernel(
    const float* __restrict__ z_t, const float* __restrict__ z_o,
    const float* __restrict__ W1,  const float* __restrict__ b1)
{
    __shared__ float As[2][32][68];   // [buf][k][m]; 272B row (16B mult)
    __shared__ float Bs[2][32][36];   // [buf][k][n]; 144B row (16B mult)

    const int tid = threadIdx.x;
    const int mt  = blockIdx.y;             // 0..23
    const int n0  = blockIdx.x << 5;        // 0..480
    const int z   = blockIdx.z;             // k-plane
    const bool isHo = (mt >= 16);
    const int m0 = (isHo ? (mt - 16) : mt) << 6;
    const float* A = isHo ? z_o : z_t;
    const float* B = isHo ? (W1 + (u64)DD * HH) : W1;
    float* C = isHo ? (z ? g_ho1 : g_ho0) : (z ? g_ht1 : g_ht0);

    // A staging: m = tid&63, k-half = (tid>>6)*16, 4 float4 along k
    const int am  = tid & 63;
    const int akh = (tid >> 6) << 4;        // 0 or 16
    // B staging: k row = tid>>2 (0..31), n base = (tid&3)*8, 2 float4
    const int bk = tid >> 2;
    const int bn = (tid & 3) << 3;

    // compute: n quad at tx*4, m quad at ty*4
    const int tx = tid & 7;
    const int ty = tid >> 3;                // 0..15

    u64 acc[4][2];
    #pragma unroll
    for (int m = 0; m < 4; m++) { acc[m][0] = 0ull; acc[m][1] = 0ull; }

    const float* aptr = &A[(u64)(m0 + am) * DD + (z << 7) + akh];
    const float* bptr = &B[(u64)((z << 7) + bk) * HH + n0 + bn];

    float4 va[4], vb[2];

    // ---- prologue: stage 0 ----
    #pragma unroll
    for (int q = 0; q < 4; q++)
        va[q] = *reinterpret_cast<const float4*>(aptr + (q << 2));
    vb[0] = *reinterpret_cast<const float4*>(bptr);
    vb[1] = *reinterpret_cast<const float4*>(bptr + 4);

    #pragma unroll
    for (int q = 0; q < 4; q++) {
        As[0][akh + (q << 2) + 0][am] = va[q].x;
        As[0][akh + (q << 2) + 1][am] = va[q].y;
        As[0][akh + (q << 2) + 2][am] = va[q].z;
        As[0][akh + (q << 2) + 3][am] = va[q].w;
    }
    *reinterpret_cast<float4*>(&Bs[0][bk][bn])     = vb[0];
    *reinterpret_cast<float4*>(&Bs[0][bk][bn + 4]) = vb[1];
    __syncthreads();

    #pragma unroll 1
    for (int kb = 0; kb < 4; kb++) {        // 4 x 32 = this plane's 128 k
        const int cur = kb & 1, nxt = cur ^ 1;

        if (kb < 3) {   // next stage's global loads, hidden under compute
            const float* ap = aptr + ((kb + 1) << 5);
            #pragma unroll
            for (int q = 0; q < 4; q++)
                va[q] = *reinterpret_cast<const float4*>(ap + (q << 2));
            const float* bp = bptr + (u64)((kb + 1) << 5) * HH;
            vb[0] = *reinterpret_cast<const float4*>(bp);
            vb[1] = *reinterpret_cast<const float4*>(bp + 4);
        }

        // ---- depth-2 pipelined 32-k compute ----
        float4     a0 = *reinterpret_cast<const float4*>(&As[cur][0][ty << 2]);
        ulonglong2 q0 = *reinterpret_cast<const ulonglong2*>(&Bs[cur][0][tx << 2]);
        float4     a1 = *reinterpret_cast<const float4*>(&As[cur][1][ty << 2]);
        ulonglong2 q1 = *reinterpret_cast<const ulonglong2*>(&Bs[cur][1][tx << 2]);

        #pragma unroll
        for (int k = 0; k < 32; k++) {
            float4 a2; ulonglong2 q2;
            if (k < 30) {
                a2 = *reinterpret_cast<const float4*>(&As[cur][k + 2][ty << 2]);
                q2 = *reinterpret_cast<const ulonglong2*>(&Bs[cur][k + 2][tx << 2]);
            }
            u64 ad0, ad1, ad2, ad3;
            asm("mov.b64 %0,{%1,%1};" : "=l"(ad0) : "f"(a0.x));
            asm("mov.b64 %0,{%1,%1};" : "=l"(ad1) : "f"(a0.y));
            asm("mov.b64 %0,{%1,%1};" : "=l"(ad2) : "f"(a0.z));
            asm("mov.b64 %0,{%1,%1};" : "=l"(ad3) : "f"(a0.w));
            acc[0][0] = fma2(ad0, q0.x, acc[0][0]);
            acc[0][1] = fma2(ad0, q0.y, acc[0][1]);
            acc[1][0] = fma2(ad1, q0.x, acc[1][0]);
            acc[1][1] = fma2(ad1, q0.y, acc[1][1]);
            acc[2][0] = fma2(ad2, q0.x, acc[2][0]);
            acc[2][1] = fma2(ad2, q0.y, acc[2][1]);
            acc[3][0] = fma2(ad3, q0.x, acc[3][0]);
            acc[3][1] = fma2(ad3, q0.y, acc[3][1]);
            a0 = a1; q0 = q1;
            a1 = a2; q1 = q2;
        }

        if (kb < 3) {   // store into the other buffer, then sync
            #pragma unroll
            for (int q = 0; q < 4; q++) {
                As[nxt][akh + (q << 2) + 0][am] = va[q].x;
                As[nxt][akh + (q << 2) + 1][am] = va[q].y;
                As[nxt][akh + (q << 2) + 2][am] = va[q].z;
                As[nxt][akh + (q << 2) + 3][am] = va[q].w;
            }
            *reinterpret_cast<float4*>(&Bs[nxt][bk][bn])     = vb[0];
            *reinterpret_cast<float4*>(&Bs[nxt][bk][bn + 4]) = vb[1];
            __syncthreads();
        }
    }

    // epilogue: plain stores to this plane's buffer; bias only on plane 0
    float4 bv = make_float4(0.f, 0.f, 0.f, 0.f);
    if (isHo && z == 0) bv = *reinterpret_cast<const float4*>(&b1[n0 + (tx << 2)]);

    #pragma unroll
    for (int m = 0; m < 4; m++) {
        float2 p0 = *reinterpret_cast<float2*>(&acc[m][0]);
        float2 p1 = *reinterpret_cast<float2*>(&acc[m][1]);
        float4 r = make_float4(p0.x + bv.x, p0.y + bv.y, p1.x + bv.z, p1.y + bv.w);
        int row = m0 + (ty << 2) + m;
        *reinterpret_cast<float4*>(&C[(u64)row * HH + n0 + (tx << 2)]) = r;
    }
}

// ---------------------------------------------------------------------------
// Per-row linear terms over summed planes:
// ct[t] = 0.505*<ht0+ht1, W2>, co[o] = 0.505*<ho0+ho1, W2> + b2
// ---------------------------------------------------------------------------
__global__ __launch_bounds__(256) void reduce_kernel(
    const float* __restrict__ W2, const float* __restrict__ b2)
{
    int warp = (blockIdx.x * blockDim.x + threadIdx.x) >> 5;
    int lane = threadIdx.x & 31;
    const float *r0, *r1;
    float* dst;
    float extra = 0.f;
    if (warp < TT) {
        r0 = g_ht0 + (u64)warp * HH; r1 = g_ht1 + (u64)warp * HH; dst = g_ct + warp;
    } else {
        r0 = g_ho0 + (u64)(warp - TT) * HH; r1 = g_ho1 + (u64)(warp - TT) * HH;
        dst = g_co + (warp - TT); extra = b2[0];
    }
    float s = 0.f;
    #pragma unroll
    for (int i = 0; i < 4; i++) {
        float4 v0 = *reinterpret_cast<const float4*>(&r0[(lane + 32 * i) << 2]);
        float4 v1 = *reinterpret_cast<const float4*>(&r1[(lane + 32 * i) << 2]);
        float4 w  = *reinterpret_cast<const float4*>(&W2[(lane + 32 * i) << 2]);
        s += (v0.x + v1.x) * w.x + (v0.y + v1.y) * w.y
           + (v0.z + v1.z) * w.z + (v0.w + v1.w) * w.w;
    }
    #pragma unroll
    for (int off = 16; off; off >>= 1) s += __shfl_xor_sync(0xffffffffu, s, off);
    if (lane == 0) *dst = 0.505f * s + extra;
}

// ---------------------------------------------------------------------------
// Pairwise kernel, H-SPLIT by 2 (grid.z): plane z covers h in [z*256,...).
// Both planes atomicAdd into pre-zeroed out; z=0 adds ct+co.
// 64x64 tile, 256 threads, micro 4t x 4o, 256 CTAs -> ~14 warps/SM.
// Staging sums the two gemm k-planes on the fly. Depth-2 hq pipeline.
// ---------------------------------------------------------------------------
__global__ __launch_bounds__(256) void pair_kernel(
    const float* __restrict__ W2, float* __restrict__ out)
{
    __shared__ float4 sA[16][65];      // [hq][t], float4 = 4 h
    __shared__ float4 sB[16][65];      // [hq][o]
    __shared__ float4 sW[HH / 4];      // 0.495*W2 quads

    const int tid = threadIdx.x;
    const int tx = tid & 15;           // o lane (o = tx + 16j)
    const int ty = tid >> 4;           // t lane (t = ty + 16i)
    const int t0 = blockIdx.y << 6;
    const int o0 = blockIdx.x << 6;
    const int z  = blockIdx.z;         // h-half
    const int cz = z << 2;             // first chunk of this half

    if (tid < HH / 4) {
        float4 w = *reinterpret_cast<const float4*>(&W2[tid << 2]);
        w.x *= 0.495f; w.y *= 0.495f; w.z *= 0.495f; w.w *= 0.495f;
        sW[tid] = w;
    }

    u64 acc[4][4];
    #pragma unroll
    for (int i = 0; i < 4; i++)
        #pragma unroll
        for (int j = 0; j < 4; j++) acc[i][j] = 0ull;

    const int hs = tid & 15;           // hq for staging
    const int ts = tid >> 4;           // 0..15
    const u64 SMASK = 0x7fffffff7fffffffULL;

    u64 ia[4], ib[4];
    #pragma unroll
    for (int r = 0; r < 4; r++) {
        ia[r] = (u64)(t0 + ts + (r << 4)) * HH + (cz << 6) + (hs << 2);
        ib[r] = (u64)(o0 + ts + (r << 4)) * HH + (cz << 6) + (hs << 2);
    }

    float4 va[4], vb[4];
    #pragma unroll
    for (int r = 0; r < 4; r++) {
        va[r] = f4add(*reinterpret_cast<const float4*>(g_ht0 + ia[r]),
                      *reinterpret_cast<const float4*>(g_ht1 + ia[r]));
        vb[r] = f4add(*reinterpret_cast<const float4*>(g_ho0 + ib[r]),
                      *reinterpret_cast<const float4*>(g_ho1 + ib[r]));
    }

    #pragma unroll 1
    for (int cc = 0; cc < 4; cc++) {   // 4 chunks of 64 h in this half
        const int c = cz + cc;
        __syncthreads();
        #pragma unroll
        for (int r = 0; r < 4; r++) {
            sA[hs][ts + (r << 4)] = va[r];
            sB[hs][ts + (r << 4)] = vb[r];
        }
        __syncthreads();

        if (cc < 3) {                  // prefetch next chunk under compute
            int off = (cc + 1) << 6;
            #pragma unroll
            for (int r = 0; r < 4; r++) {
                va[r] = f4add(*reinterpret_cast<const float4*>(g_ht0 + ia[r] + off),
                              *reinterpret_cast<const float4*>(g_ht1 + ia[r] + off));
                vb[r] = f4add(*reinterpret_cast<const float4*>(g_ho0 + ib[r] + off),
                              *reinterpret_cast<const float4*>(g_ho1 + ib[r] + off));
            }
        }

        // ---- depth-2 pipelined hq loop ----
        ulonglong2 w = *reinterpret_cast<const ulonglong2*>(&sW[c << 4]);
        ulonglong2 a[4], b[4];
        #pragma unroll
        for (int i = 0; i < 4; i++)
            a[i] = *reinterpret_cast<const ulonglong2*>(&sA[0][ty + (i << 4)]);
        #pragma unroll
        for (int j = 0; j < 4; j++)
            b[j] = *reinterpret_cast<const ulonglong2*>(&sB[0][tx + (j << 4)]);

        #pragma unroll
        for (int hq = 0; hq < 16; hq++) {
            ulonglong2 wn, an[4], bn[4];
            if (hq < 15) {
                wn = *reinterpret_cast<const ulonglong2*>(&sW[(c << 4) + hq + 1]);
                #pragma unroll
                for (int i = 0; i < 4; i++)
                    an[i] = *reinterpret_cast<const ulonglong2*>(&sA[hq + 1][ty + (i << 4)]);
                #pragma unroll
                for (int j = 0; j < 4; j++)
                    bn[j] = *reinterpret_cast<const ulonglong2*>(&sB[hq + 1][tx + (j << 4)]);
            }

            #pragma unroll
            for (int i = 0; i < 4; i++)
                #pragma unroll
                for (int j = 0; j < 4; j++) {
                    u64 x = add2(a[i].x, b[j].x) & SMASK;
                    acc[i][j] = fma2(x, w.x, acc[i][j]);
                    u64 y = add2(a[i].y, b[j].y) & SMASK;
                    acc[i][j] = fma2(y, w.y, acc[i][j]);
                }

            if (hq < 15) {
                w = wn;
                #pragma unroll
                for (int i = 0; i < 4; i++) a[i] = an[i];
                #pragma unroll
                for (int j = 0; j < 4; j++) b[j] = bn[j];
            }
        }
    }

    float ctv[4], cov[4];
    if (z == 0) {
        #pragma unroll
        for (int i = 0; i < 4; i++) ctv[i] = g_ct[t0 + ty + (i << 4)];
        #pragma unroll
        for (int j = 0; j < 4; j++) cov[j] = g_co[o0 + tx + (j << 4)];
    } else {
        #pragma unroll
        for (int i = 0; i < 4; i++) ctv[i] = 0.f;
        #pragma unroll
        for (int j = 0; j < 4; j++) cov[j] = 0.f;
    }
    #pragma unroll
    for (int i = 0; i < 4; i++)
        #pragma unroll
        for (int j = 0; j < 4; j++) {
            float2 p = *reinterpret_cast<float2*>(&acc[i][j]);
            atomicAdd(&out[(u64)(t0 + ty + (i << 4)) * OO + o0 + tx + (j << 4)],
                      ctv[i] + cov[j] + p.x + p.y);
        }
}

extern "C" void kernel_launch(void* const* d_in, const int* in_sizes, int n_in,
                              void* d_out, int out_size)
{
    const float* z_t = (const float*)d_in[0];   // [1024,256]
    const float* z_o = (const float*)d_in[1];   // [512,256]
    const float* W1  = (const float*)d_in[2];   // [512,512]
    const float* b1  = (const float*)d_in[3];   // [512]
    const float* W2  = (const float*)d_in[4];   // [512,1]
    const float* b2  = (const float*)d_in[5];   // [1]
    float* out = (float*)d_out;                 // [1024,512]

    zero_kernel<<<TT * OO / 1024, 256>>>((float4*)out);
    gemm_kernel<<<dim3(16, 24, 2), 128>>>(z_t, z_o, W1, b1);
    reduce_kernel<<<192, 256>>>(W2, b2);
    pair_kernel<<<dim3(OO / 64, TT / 64, 2), 256>>>(W2, out);
}